// round 14
// baseline (speedup 1.0000x reference)
#include <cuda_runtime.h>
#include <cuda_fp16.h>
#include <stdint.h>
#include <math.h>

typedef unsigned int u32;

#define T_TOK 2048
#define H_DIM 2048
#define NH 16
#define HD 128
#define QKV_N (3 * H_DIM)   // 6144
#define EPS 1e-6f
#define ATT_SCALE 0.08838834764831843f  // 128^-0.5

// ---------------- scratch (static device globals; no allocation) -------------
__device__ float  g_qkv[T_TOK * QKV_N];     // [T, 3H] fp32
__device__ __half g_qh[T_TOK * H_DIM];      // post norm+rope, pre-scaled
__device__ __half g_kh[T_TOK * H_DIM];
__device__ __half g_vh[T_TOK * H_DIM];
__device__ __half g_hid_h[T_TOK * H_DIM];
__device__ __half g_wqkv_h[H_DIM * QKV_N];
__device__ __half g_wo_h[H_DIM * H_DIM];
__device__ __half g_attn_h[T_TOK * H_DIM];
__device__ float  g_opart[2 * T_TOK * H_DIM];        // split-KV partial O
__device__ float  g_ml[2 * T_TOK * NH * 2];          // per-row (m, l) per half

// ---------------- merged f32 -> f16 conversion (3 tensors, 1 launch) ---------
#define CVT_N1 (T_TOK * H_DIM / 4)     // hidden
#define CVT_N2 (H_DIM * QKV_N / 4)     // w_qkv
#define CVT_N3 (H_DIM * H_DIM / 4)     // w_o
__global__ __launch_bounds__(256) void convert_all(
    const float* __restrict__ in1, __half* __restrict__ out1,
    const float* __restrict__ in2, __half* __restrict__ out2,
    const float* __restrict__ in3, __half* __restrict__ out3)
{
    int i = blockIdx.x * 256 + threadIdx.x;
    const float* in; __half* out; int idx;
    if (i < CVT_N1)                 { in = in1; out = out1; idx = i; }
    else if (i < CVT_N1 + CVT_N2)   { in = in2; out = out2; idx = i - CVT_N1; }
    else if (i < CVT_N1 + CVT_N2 + CVT_N3) { in = in3; out = out3; idx = i - CVT_N1 - CVT_N2; }
    else return;
    float4 v = ((const float4*)in)[idx];
    ((__half2*)out)[2 * idx]     = __floats2half2_rn(v.x, v.y);
    ((__half2*)out)[2 * idx + 1] = __floats2half2_rn(v.z, v.w);
}

// ------------------------- PTX wrappers --------------------------------------
__device__ __forceinline__ void cp_async16(void* sptr, const void* gptr) {
    u32 s = (u32)__cvta_generic_to_shared(sptr);
    asm volatile("cp.async.cg.shared.global [%0], [%1], 16;\n" :: "r"(s), "l"(gptr));
}
__device__ __forceinline__ void cp_commit() {
    asm volatile("cp.async.commit_group;\n");
}
template <int N>
__device__ __forceinline__ void cp_wait() {
    asm volatile("cp.async.wait_group %0;\n" :: "n"(N));
}
__device__ __forceinline__ void ldmatrix_x4(u32* r, const void* sptr) {
    u32 s = (u32)__cvta_generic_to_shared(sptr);
    asm volatile("ldmatrix.sync.aligned.m8n8.x4.shared.b16 {%0,%1,%2,%3}, [%4];\n"
                 : "=r"(r[0]), "=r"(r[1]), "=r"(r[2]), "=r"(r[3]) : "r"(s));
}
__device__ __forceinline__ void ldmatrix_x4_trans(u32* r, const void* sptr) {
    u32 s = (u32)__cvta_generic_to_shared(sptr);
    asm volatile("ldmatrix.sync.aligned.m8n8.x4.trans.shared.b16 {%0,%1,%2,%3}, [%4];\n"
                 : "=r"(r[0]), "=r"(r[1]), "=r"(r[2]), "=r"(r[3]) : "r"(s));
}
__device__ __forceinline__ void mma16816(float* d, const u32* a, const u32* b) {
    asm volatile(
        "mma.sync.aligned.m16n8k16.row.col.f32.f16.f16.f32 "
        "{%0,%1,%2,%3}, {%4,%5,%6,%7}, {%8,%9}, {%0,%1,%2,%3};\n"
        : "+f"(d[0]), "+f"(d[1]), "+f"(d[2]), "+f"(d[3])
        : "r"(a[0]), "r"(a[1]), "r"(a[2]), "r"(a[3]), "r"(b[0]), "r"(b[1]));
}
__device__ __forceinline__ u32 packh2(float a, float b) {
    __half2 h = __floats2half2_rn(a, b);
    return *reinterpret_cast<u32*>(&h);
}

// ---- fp16 GEMM: CTA 128x128, 4 warps (64x64), BK=32, 4-stage, 1 barrier -----
#define ASTRIDE 40
#define BSTRIDE 136
#define HG_STAGE_A (128 * ASTRIDE)           // halves
#define HG_STAGE_B (32 * BSTRIDE)
#define HG_STAGE   (HG_STAGE_A + HG_STAGE_B) // 9472 halves
#define HG_STAGES  4
#define HG_SMEM_BYTES (HG_STAGES * HG_STAGE * 2)   // 75776 B

__global__ __launch_bounds__(128, 2) void hgemm_w64(
    const __half* __restrict__ A, const __half* __restrict__ B,
    float* __restrict__ C, int M, int N, int K)
{
    extern __shared__ __align__(16) __half hsm[];

    const int tid  = threadIdx.x;
    const int wid  = tid >> 5;
    const int lane = tid & 31;
    const int wm = (wid & 1) * 64;
    const int wn = (wid >> 1) * 64;
    const int bRow = blockIdx.y * 128;
    const int bCol = blockIdx.x * 128;

    const int a_r0 = tid >> 2;
    const int a_c  = (tid & 3) * 8;
    const int b_r0 = tid >> 4;
    const int b_c  = (tid & 15) * 8;

    float acc[4][8][4];
    #pragma unroll
    for (int mi = 0; mi < 4; mi++)
        #pragma unroll
        for (int nf = 0; nf < 8; nf++)
            #pragma unroll
            for (int r = 0; r < 4; r++) acc[mi][nf][r] = 0.f;

    const int NT = K / 32;

    auto load_tile = [&](int kt, int st) {
        __half* As = hsm + st * HG_STAGE;
        __half* Bs = As + HG_STAGE_A;
        const int kb = kt * 32;
        #pragma unroll
        for (int p = 0; p < 4; p++) {
            int ar = a_r0 + p * 32;
            cp_async16(&As[ar * ASTRIDE + a_c], A + (size_t)(bRow + ar) * K + kb + a_c);
            int br = b_r0 + p * 8;
            cp_async16(&Bs[br * BSTRIDE + b_c], B + (size_t)(kb + br) * N + bCol + b_c);
        }
    };

    load_tile(0, 0); cp_commit();
    load_tile(1, 1); cp_commit();
    load_tile(2, 2); cp_commit();

    int st = 0;
    for (int kt = 0; kt < NT; kt++) {
        cp_wait<2>();
        __syncthreads();

        if (kt + 3 < NT) load_tile(kt + 3, (st + 3) & 3);
        cp_commit();

        const __half* As = hsm + st * HG_STAGE;
        const __half* Bs = As + HG_STAGE_A;

        u32 a[2][4][4];
        u32 b[2][8][2];
        #pragma unroll
        for (int s = 0; s < 2; s++) {
            const int ko = s * 16;
            #pragma unroll
            for (int mi = 0; mi < 4; mi++)
                ldmatrix_x4(a[s][mi],
                    &As[(wm + mi * 16 + (lane & 15)) * ASTRIDE + ko + (lane >> 4) * 8]);
            #pragma unroll
            for (int ng = 0; ng < 4; ng++) {
                u32 r[4];
                ldmatrix_x4_trans(r,
                    &Bs[(ko + (lane & 15)) * BSTRIDE + wn + ng * 16 + (lane >> 4) * 8]);
                b[s][2 * ng][0]     = r[0]; b[s][2 * ng][1]     = r[1];
                b[s][2 * ng + 1][0] = r[2]; b[s][2 * ng + 1][1] = r[3];
            }
        }
        #pragma unroll
        for (int s = 0; s < 2; s++)
            #pragma unroll
            for (int mi = 0; mi < 4; mi++)
                #pragma unroll
                for (int nf = 0; nf < 8; nf++)
                    mma16816(acc[mi][nf], a[s][mi], b[s][nf]);

        st = (st + 1) & 3;
    }

    #pragma unroll
    for (int mi = 0; mi < 4; mi++) {
        const int row0 = bRow + wm + mi * 16 + (lane >> 2);
        #pragma unroll
        for (int nf = 0; nf < 8; nf++) {
            const int col = bCol + wn + nf * 8 + (lane & 3) * 2;
            *(float2*)&C[(size_t)row0 * N + col]       = make_float2(acc[mi][nf][0], acc[mi][nf][1]);
            *(float2*)&C[(size_t)(row0 + 8) * N + col] = make_float2(acc[mi][nf][2], acc[mi][nf][3]);
        }
    }
}

// -------- fused RMSNorm + RoPE -> fp16 q (pre-scaled), k, v ------------------
__global__ __launch_bounds__(256) void norm_rope_kernel(
    const float* __restrict__ qkv, const int* __restrict__ positions,
    const float* __restrict__ qw, const float* __restrict__ kw,
    __half* __restrict__ qh, __half* __restrict__ kh, __half* __restrict__ vh)
{
    const int t = blockIdx.x;
    const int tid = threadIdx.x;
    const float* row = qkv + (size_t)t * QKV_N;

    __shared__ float red[256];
    __shared__ float s_invq, s_invk;

    float sq = 0.f, sk = 0.f;
    for (int i = tid; i < H_DIM; i += 256) {
        float a = row[i];          sq = fmaf(a, a, sq);
        float b = row[H_DIM + i];  sk = fmaf(b, b, sk);
    }
    red[tid] = sq; __syncthreads();
    for (int s = 128; s > 0; s >>= 1) {
        if (tid < s) red[tid] += red[tid + s];
        __syncthreads();
    }
    if (tid == 0) s_invq = rsqrtf(red[0] / (float)H_DIM + EPS);
    __syncthreads();
    red[tid] = sk; __syncthreads();
    for (int s = 128; s > 0; s >>= 1) {
        if (tid < s) red[tid] += red[tid + s];
        __syncthreads();
    }
    if (tid == 0) s_invk = rsqrtf(red[0] / (float)H_DIM + EPS);
    __syncthreads();

    const float invq = s_invq, invk = s_invk;
    const float pos = (float)positions[t];

    for (int p = tid; p < NH * (HD / 2); p += 256) {
        const int h = p >> 6;
        const int d = p & 63;
        float invf = exp2f(-0.29580576f * (float)d);  // 500000^(-d/64)
        float ang = pos * invf;
        float c, s;
        sincosf(ang, &s, &c);

        const int i1 = h * HD + d;
        const int i2 = i1 + 64;

        float q1 = row[i1] * invq * qw[i1];
        float q2 = row[i2] * invq * qw[i2];
        float k1 = row[H_DIM + i1] * invk * kw[i1];
        float k2 = row[H_DIM + i2] * invk * kw[i2];

        const size_t ob = (size_t)t * H_DIM + h * HD + d;
        qh[ob]      = __float2half((q1 * c - q2 * s) * ATT_SCALE);
        qh[ob + 64] = __float2half((q2 * c + q1 * s) * ATT_SCALE);
        kh[ob]      = __float2half(k1 * c - k2 * s);
        kh[ob + 64] = __float2half(k2 * c + k1 * s);
    }

    for (int i = tid; i < H_DIM; i += 256)
        vh[(size_t)t * H_DIM + i] = __float2half(row[2 * H_DIM + i]);
}

// ---- fp16 MMA flash attention, BQ=64, 4 warps, split-KV, 3 CTAs/SM ----------
// grid (64, 16): blockIdx.x -> (qt 0..31, half), LPT-ordered.
// Q is staged into the KV smem area, fragments extracted, smem recycled.
#define FQ 64
#define BK 64
#define KSTR 136
#define FLASH_SMEM_BYTES (4 * BK * KSTR * 2)   // 69632 B

__global__ __launch_bounds__(128, 3) void flash_mma(
    const __half* __restrict__ qh, const __half* __restrict__ kh,
    const __half* __restrict__ vh, float* __restrict__ op,
    float* __restrict__ ml)
{
    const int slot = (int)blockIdx.x;            // 0..63
    const int qt   = 31 - (slot >> 1);           // heaviest (qt=31) first
    const int half = slot & 1;
    const int h = blockIdx.y;
    const int tid = threadIdx.x, wid = tid >> 5, lane = tid & 31;
    const int wm = wid * 16;

    const int nt  = qt + 1;
    const int mid = (nt + 1) >> 1;
    const int kb0 = half ? mid : 0;
    const int kb1 = half ? nt : mid;

    extern __shared__ __align__(16) __half fsm[];
    __half* Ks = fsm;                    // 2 x (64 x 136)
    __half* Vs = Ks + 2 * BK * KSTR;     // 2 x (64 x 136)

    // ---- stage Q into smem (recycled KV area), extract fragments ----
    {
        const int qr = tid >> 1;
        const int qc = (tid & 1) * 8;
        const size_t qbase = (size_t)(qt * FQ + qr) * H_DIM + h * HD;
        #pragma unroll
        for (int i = 0; i < 8; i++)
            cp_async16(&fsm[qr * KSTR + (qc + i) * 8], &qh[qbase + (qc + i) * 8]);
    }
    cp_commit();
    cp_wait<0>();
    __syncthreads();

    u32 qf[8][4];
    #pragma unroll
    for (int ks = 0; ks < 8; ks++)
        ldmatrix_x4(qf[ks], &fsm[(wm + (lane & 15)) * KSTR + ks * 16 + (lane >> 4) * 8]);
    __syncthreads();   // everyone done reading Q; smem may be overwritten

    // ---- KV prologue ----
    const int r  = tid >> 1;
    const int c0 = (tid & 1) * 8;
    if (kb0 < kb1) {
        const size_t base = (size_t)(kb0 * BK + r) * H_DIM + h * HD;
        #pragma unroll
        for (int i = 0; i < 8; i++) {
            cp_async16(&Ks[r * KSTR + (c0 + i) * 8], &kh[base + (c0 + i) * 8]);
            cp_async16(&Vs[r * KSTR + (c0 + i) * 8], &vh[base + (c0 + i) * 8]);
        }
    }
    cp_commit();

    float o[16][4];
    #pragma unroll
    for (int nf = 0; nf < 16; nf++)
        #pragma unroll
        for (int rr = 0; rr < 4; rr++) o[nf][rr] = 0.f;
    // init at -1e20: fully-masked/empty halves yield p = 0, l = 0
    float m0 = -1e20f, m1 = -1e20f, l0 = 0.f, l1 = 0.f;

    for (int kb = kb0; kb < kb1; kb++) {
        cp_wait<0>();
        __syncthreads();

        if (kb + 1 < kb1) {
            const int nb = (kb + 1 - kb0) & 1;
            const size_t base = (size_t)((kb + 1) * BK + r) * H_DIM + h * HD;
            #pragma unroll
            for (int i = 0; i < 8; i++) {
                cp_async16(&Ks[nb * BK * KSTR + r * KSTR + (c0 + i) * 8], &kh[base + (c0 + i) * 8]);
                cp_async16(&Vs[nb * BK * KSTR + r * KSTR + (c0 + i) * 8], &vh[base + (c0 + i) * 8]);
            }
            cp_commit();
        }

        const __half* Kb = Ks + ((kb - kb0) & 1) * BK * KSTR;
        const __half* Vb = Vs + ((kb - kb0) & 1) * BK * KSTR;

        float s[8][4];
        #pragma unroll
        for (int nf = 0; nf < 8; nf++)
            #pragma unroll
            for (int rr = 0; rr < 4; rr++) s[nf][rr] = 0.f;

        #pragma unroll
        for (int ks = 0; ks < 8; ks++) {
            u32 bf[8][2];
            #pragma unroll
            for (int ng = 0; ng < 4; ng++) {
                u32 rr[4];
                ldmatrix_x4(rr, &Kb[(ng * 16 + (lane & 7) + ((lane >> 4) << 3)) * KSTR
                                    + ks * 16 + (((lane >> 3) & 1) << 3)]);
                bf[2 * ng][0] = rr[0];     bf[2 * ng][1] = rr[1];
                bf[2 * ng + 1][0] = rr[2]; bf[2 * ng + 1][1] = rr[3];
            }
            #pragma unroll
            for (int nf = 0; nf < 8; nf++)
                mma16816(s[nf], qf[ks], bf[nf]);
        }

        // causal mask: only the diagonal tile (kb == qt)
        if (kb == qt) {
            const int grow = qt * FQ + wm + (lane >> 2);
            #pragma unroll
            for (int nf = 0; nf < 8; nf++) {
                const int col = kb * BK + nf * 8 + (lane & 3) * 2;
                if (col     > grow)     s[nf][0] = -1e30f;
                if (col + 1 > grow)     s[nf][1] = -1e30f;
                if (col     > grow + 8) s[nf][2] = -1e30f;
                if (col + 1 > grow + 8) s[nf][3] = -1e30f;
            }
        }

        float mx0 = -1e30f, mx1 = -1e30f;
        #pragma unroll
        for (int nf = 0; nf < 8; nf++) {
            mx0 = fmaxf(mx0, fmaxf(s[nf][0], s[nf][1]));
            mx1 = fmaxf(mx1, fmaxf(s[nf][2], s[nf][3]));
        }
        mx0 = fmaxf(mx0, __shfl_xor_sync(0xffffffffu, mx0, 1));
        mx0 = fmaxf(mx0, __shfl_xor_sync(0xffffffffu, mx0, 2));
        mx1 = fmaxf(mx1, __shfl_xor_sync(0xffffffffu, mx1, 1));
        mx1 = fmaxf(mx1, __shfl_xor_sync(0xffffffffu, mx1, 2));

        const float mn0 = fmaxf(m0, mx0), mn1 = fmaxf(m1, mx1);
        const float a0 = __expf(m0 - mn0), a1 = __expf(m1 - mn1);
        m0 = mn0; m1 = mn1;

        float ps0 = 0.f, ps1 = 0.f;
        #pragma unroll
        for (int nf = 0; nf < 8; nf++) {
            s[nf][0] = __expf(s[nf][0] - m0); ps0 += s[nf][0];
            s[nf][1] = __expf(s[nf][1] - m0); ps0 += s[nf][1];
            s[nf][2] = __expf(s[nf][2] - m1); ps1 += s[nf][2];
            s[nf][3] = __expf(s[nf][3] - m1); ps1 += s[nf][3];
        }
        ps0 += __shfl_xor_sync(0xffffffffu, ps0, 1);
        ps0 += __shfl_xor_sync(0xffffffffu, ps0, 2);
        ps1 += __shfl_xor_sync(0xffffffffu, ps1, 1);
        ps1 += __shfl_xor_sync(0xffffffffu, ps1, 2);
        l0 = l0 * a0 + ps0;
        l1 = l1 * a1 + ps1;

        #pragma unroll
        for (int nf = 0; nf < 16; nf++) {
            o[nf][0] *= a0; o[nf][1] *= a0;
            o[nf][2] *= a1; o[nf][3] *= a1;
        }

        #pragma unroll
        for (int s4 = 0; s4 < 4; s4++) {
            u32 pa[4];
            pa[0] = packh2(s[2 * s4][0],     s[2 * s4][1]);
            pa[1] = packh2(s[2 * s4][2],     s[2 * s4][3]);
            pa[2] = packh2(s[2 * s4 + 1][0], s[2 * s4 + 1][1]);
            pa[3] = packh2(s[2 * s4 + 1][2], s[2 * s4 + 1][3]);
            #pragma unroll
            for (int ng = 0; ng < 8; ng++) {
                u32 rr[4];
                ldmatrix_x4_trans(rr, &Vb[(s4 * 16 + (lane & 15)) * KSTR
                                          + ng * 16 + (lane >> 4) * 8]);
                mma16816(o[2 * ng],     pa, &rr[0]);
                mma16816(o[2 * ng + 1], pa, &rr[2]);
            }
        }
    }

    // epilogue: write UNNORMALIZED partial O + (m, l) per row
    const int row0 = qt * FQ + wm + (lane >> 2);
    float* opb = op + (size_t)half * T_TOK * H_DIM;
    #pragma unroll
    for (int nf = 0; nf < 16; nf++) {
        const int col = h * HD + nf * 8 + (lane & 3) * 2;
        *(float2*)&opb[(size_t)row0 * H_DIM + col]       = make_float2(o[nf][0], o[nf][1]);
        *(float2*)&opb[(size_t)(row0 + 8) * H_DIM + col] = make_float2(o[nf][2], o[nf][3]);
    }
    if ((lane & 3) == 0) {
        float* mlb = ml + (size_t)half * T_TOK * NH * 2;
        mlb[((size_t)row0 * NH + h) * 2]           = m0;
        mlb[((size_t)row0 * NH + h) * 2 + 1]       = l0;
        mlb[((size_t)(row0 + 8) * NH + h) * 2]     = m1;
        mlb[((size_t)(row0 + 8) * NH + h) * 2 + 1] = l1;
    }
}

// ----------------------- split-KV combine ------------------------------------
__global__ __launch_bounds__(256) void flash_combine(
    const float* __restrict__ op, const float* __restrict__ ml,
    __half* __restrict__ oh)
{
    const int t = blockIdx.x;
    const int tid = threadIdx.x;
    #pragma unroll
    for (int e = tid; e < H_DIM; e += 256) {
        const int h = e >> 7;
        const float m0 = ml[((size_t)t * NH + h) * 2];
        const float l0 = ml[((size_t)t * NH + h) * 2 + 1];
        const float m1 = ml[(size_t)T_TOK * NH * 2 + ((size_t)t * NH + h) * 2];
        const float l1 = ml[(size_t)T_TOK * NH * 2 + ((size_t)t * NH + h) * 2 + 1];
        const float m  = fmaxf(m0, m1);
        const float e0 = __expf(m0 - m), e1 = __expf(m1 - m);
        const float inv = 1.f / (l0 * e0 + l1 * e1);
        const float o0 = op[(size_t)t * H_DIM + e];
        const float o1 = op[(size_t)T_TOK * H_DIM + (size_t)t * H_DIM + e];
        oh[(size_t)t * H_DIM + e] = __float2half((o0 * e0 + o1 * e1) * inv);
    }
}

// --------------------------------- launcher ----------------------------------
extern "C" void kernel_launch(void* const* d_in, const int* in_sizes, int n_in,
                              void* d_out, int out_size)
{
    const int*   positions = (const int*)  d_in[0];
    const float* hidden    = (const float*)d_in[1];
    const float* w_qkv     = (const float*)d_in[2];
    const float* q_norm_w  = (const float*)d_in[3];
    const float* k_norm_w  = (const float*)d_in[4];
    const float* w_o       = (const float*)d_in[5];
    float* out = (float*)d_out;

    float *qkv, *opart, *mlp;
    __half *qh, *kh, *vh, *hid_h, *wqkv_h, *wo_h, *attn_h;
    cudaGetSymbolAddress((void**)&qkv,    g_qkv);
    cudaGetSymbolAddress((void**)&qh,     g_qh);
    cudaGetSymbolAddress((void**)&kh,     g_kh);
    cudaGetSymbolAddress((void**)&vh,     g_vh);
    cudaGetSymbolAddress((void**)&hid_h,  g_hid_h);
    cudaGetSymbolAddress((void**)&wqkv_h, g_wqkv_h);
    cudaGetSymbolAddress((void**)&wo_h,   g_wo_h);
    cudaGetSymbolAddress((void**)&attn_h, g_attn_h);
    cudaGetSymbolAddress((void**)&opart,  g_opart);
    cudaGetSymbolAddress((void**)&mlp,    g_ml);

    // 0) fp32 -> fp16 conversions (single launch)
    {
        int total = CVT_N1 + CVT_N2 + CVT_N3;
        convert_all<<<(total + 255) / 256, 256>>>(hidden, hid_h,
                                                  w_qkv, wqkv_h, w_o, wo_h);
    }

    // 1) QKV projection (tensor cores, BK=32, 4-stage)
    {
        cudaFuncSetAttribute(hgemm_w64,
                             cudaFuncAttributeMaxDynamicSharedMemorySize,
                             HG_SMEM_BYTES);
        dim3 grid(QKV_N / 128, T_TOK / 128);
        hgemm_w64<<<grid, 128, HG_SMEM_BYTES>>>(hid_h, wqkv_h, qkv, T_TOK, QKV_N, H_DIM);
    }

    // 2) RMSNorm + RoPE -> fp16 q/k/v
    norm_rope_kernel<<<T_TOK, 256>>>(qkv, positions, q_norm_w, k_norm_w, qh, kh, vh);

    // 3) causal flash attention, split-KV BQ=64 (tensor cores) + combine
    {
        cudaFuncSetAttribute(flash_mma,
                             cudaFuncAttributeMaxDynamicSharedMemorySize,
                             FLASH_SMEM_BYTES);
        dim3 grid(2 * (T_TOK / FQ), NH);
        flash_mma<<<grid, 128, FLASH_SMEM_BYTES>>>(qh, kh, vh, opart, mlp);
        flash_combine<<<T_TOK, 256>>>(opart, mlp, attn_h);
    }

    // 4) output projection (tensor cores, BK=32, 4-stage)
    {
        dim3 grid(H_DIM / 128, T_TOK / 128);
        hgemm_w64<<<grid, 128, HG_SMEM_BYTES>>>(attn_h, wo_h, out, T_TOK, H_DIM, H_DIM);
    }
}

// round 16
// speedup vs baseline: 1.0860x; 1.0860x over previous
#include <cuda_runtime.h>
#include <cuda_fp16.h>
#include <stdint.h>
#include <math.h>

typedef unsigned int u32;

#define T_TOK 2048
#define H_DIM 2048
#define NH 16
#define HD 128
#define QKV_N (3 * H_DIM)   // 6144
#define EPS 1e-6f
#define ATT_SCALE 0.08838834764831843f  // 128^-0.5

// ---------------- scratch (static device globals; no allocation) -------------
__device__ __half g_qkvh[T_TOK * QKV_N];    // [T, 3H] fp16 (GEMM writes fp16)
__device__ __half g_qh[T_TOK * H_DIM];      // post norm+rope, pre-scaled
__device__ __half g_kh[T_TOK * H_DIM];
__device__ __half g_vh[T_TOK * H_DIM];
__device__ __half g_hid_h[T_TOK * H_DIM];
__device__ __half g_wqkv_h[H_DIM * QKV_N];
__device__ __half g_wo_h[H_DIM * H_DIM];
__device__ __half g_attn_h[T_TOK * H_DIM];
__device__ float  g_opart[2 * T_TOK * H_DIM];        // split-KV partial O
__device__ float  g_ml[2 * T_TOK * NH * 2];          // per-row (m, l) per half

// ---------------- merged f32 -> f16 conversion (3 tensors, 1 launch) ---------
#define CVT_N1 (T_TOK * H_DIM / 4)     // hidden
#define CVT_N2 (H_DIM * QKV_N / 4)     // w_qkv
#define CVT_N3 (H_DIM * H_DIM / 4)     // w_o
__global__ __launch_bounds__(256) void convert_all(
    const float* __restrict__ in1, __half* __restrict__ out1,
    const float* __restrict__ in2, __half* __restrict__ out2,
    const float* __restrict__ in3, __half* __restrict__ out3)
{
    int i = blockIdx.x * 256 + threadIdx.x;
    const float* in; __half* out; int idx;
    if (i < CVT_N1)                 { in = in1; out = out1; idx = i; }
    else if (i < CVT_N1 + CVT_N2)   { in = in2; out = out2; idx = i - CVT_N1; }
    else if (i < CVT_N1 + CVT_N2 + CVT_N3) { in = in3; out = out3; idx = i - CVT_N1 - CVT_N2; }
    else return;
    float4 v = ((const float4*)in)[idx];
    ((__half2*)out)[2 * idx]     = __floats2half2_rn(v.x, v.y);
    ((__half2*)out)[2 * idx + 1] = __floats2half2_rn(v.z, v.w);
}

// ------------------------- PTX wrappers --------------------------------------
__device__ __forceinline__ void cp_async16(void* sptr, const void* gptr) {
    u32 s = (u32)__cvta_generic_to_shared(sptr);
    asm volatile("cp.async.cg.shared.global [%0], [%1], 16;\n" :: "r"(s), "l"(gptr));
}
__device__ __forceinline__ void cp_commit() {
    asm volatile("cp.async.commit_group;\n");
}
template <int N>
__device__ __forceinline__ void cp_wait() {
    asm volatile("cp.async.wait_group %0;\n" :: "n"(N));
}
__device__ __forceinline__ void ldmatrix_x4(u32* r, const void* sptr) {
    u32 s = (u32)__cvta_generic_to_shared(sptr);
    asm volatile("ldmatrix.sync.aligned.m8n8.x4.shared.b16 {%0,%1,%2,%3}, [%4];\n"
                 : "=r"(r[0]), "=r"(r[1]), "=r"(r[2]), "=r"(r[3]) : "r"(s));
}
__device__ __forceinline__ void ldmatrix_x4_trans(u32* r, const void* sptr) {
    u32 s = (u32)__cvta_generic_to_shared(sptr);
    asm volatile("ldmatrix.sync.aligned.m8n8.x4.trans.shared.b16 {%0,%1,%2,%3}, [%4];\n"
                 : "=r"(r[0]), "=r"(r[1]), "=r"(r[2]), "=r"(r[3]) : "r"(s));
}
__device__ __forceinline__ void mma16816(float* d, const u32* a, const u32* b) {
    asm volatile(
        "mma.sync.aligned.m16n8k16.row.col.f32.f16.f16.f32 "
        "{%0,%1,%2,%3}, {%4,%5,%6,%7}, {%8,%9}, {%0,%1,%2,%3};\n"
        : "+f"(d[0]), "+f"(d[1]), "+f"(d[2]), "+f"(d[3])
        : "r"(a[0]), "r"(a[1]), "r"(a[2]), "r"(a[3]), "r"(b[0]), "r"(b[1]));
}
__device__ __forceinline__ u32 packh2(float a, float b) {
    __half2 h = __floats2half2_rn(a, b);
    return *reinterpret_cast<u32*>(&h);
}

// ---- fp16 GEMM: CTA 128x128, 4 warps (64x64), BK=32, 4-stage, 1 barrier -----
// Templated epilogue: TC = float (fp32 out) or __half (fp16 out).
#define ASTRIDE 40
#define BSTRIDE 136
#define HG_STAGE_A (128 * ASTRIDE)           // halves
#define HG_STAGE_B (32 * BSTRIDE)
#define HG_STAGE   (HG_STAGE_A + HG_STAGE_B) // 9472 halves
#define HG_STAGES  4
#define HG_SMEM_BYTES (HG_STAGES * HG_STAGE * 2)   // 75776 B

template <typename TC>
__global__ __launch_bounds__(128, 2) void hgemm_w64(
    const __half* __restrict__ A, const __half* __restrict__ B,
    TC* __restrict__ C, int M, int N, int K)
{
    extern __shared__ __align__(16) __half hsm[];

    const int tid  = threadIdx.x;
    const int wid  = tid >> 5;
    const int lane = tid & 31;
    const int wm = (wid & 1) * 64;
    const int wn = (wid >> 1) * 64;
    const int bRow = blockIdx.y * 128;
    const int bCol = blockIdx.x * 128;

    const int a_r0 = tid >> 2;
    const int a_c  = (tid & 3) * 8;
    const int b_r0 = tid >> 4;
    const int b_c  = (tid & 15) * 8;

    float acc[4][8][4];
    #pragma unroll
    for (int mi = 0; mi < 4; mi++)
        #pragma unroll
        for (int nf = 0; nf < 8; nf++)
            #pragma unroll
            for (int r = 0; r < 4; r++) acc[mi][nf][r] = 0.f;

    const int NT = K / 32;

    auto load_tile = [&](int kt, int st) {
        __half* As = hsm + st * HG_STAGE;
        __half* Bs = As + HG_STAGE_A;
        const int kb = kt * 32;
        #pragma unroll
        for (int p = 0; p < 4; p++) {
            int ar = a_r0 + p * 32;
            cp_async16(&As[ar * ASTRIDE + a_c], A + (size_t)(bRow + ar) * K + kb + a_c);
            int br = b_r0 + p * 8;
            cp_async16(&Bs[br * BSTRIDE + b_c], B + (size_t)(kb + br) * N + bCol + b_c);
        }
    };

    load_tile(0, 0); cp_commit();
    load_tile(1, 1); cp_commit();
    load_tile(2, 2); cp_commit();

    int st = 0;
    for (int kt = 0; kt < NT; kt++) {
        cp_wait<2>();
        __syncthreads();

        if (kt + 3 < NT) load_tile(kt + 3, (st + 3) & 3);
        cp_commit();

        const __half* As = hsm + st * HG_STAGE;
        const __half* Bs = As + HG_STAGE_A;

        u32 a[2][4][4];
        u32 b[2][8][2];
        #pragma unroll
        for (int s = 0; s < 2; s++) {
            const int ko = s * 16;
            #pragma unroll
            for (int mi = 0; mi < 4; mi++)
                ldmatrix_x4(a[s][mi],
                    &As[(wm + mi * 16 + (lane & 15)) * ASTRIDE + ko + (lane >> 4) * 8]);
            #pragma unroll
            for (int ng = 0; ng < 4; ng++) {
                u32 r[4];
                ldmatrix_x4_trans(r,
                    &Bs[(ko + (lane & 15)) * BSTRIDE + wn + ng * 16 + (lane >> 4) * 8]);
                b[s][2 * ng][0]     = r[0]; b[s][2 * ng][1]     = r[1];
                b[s][2 * ng + 1][0] = r[2]; b[s][2 * ng + 1][1] = r[3];
            }
        }
        #pragma unroll
        for (int s = 0; s < 2; s++)
            #pragma unroll
            for (int mi = 0; mi < 4; mi++)
                #pragma unroll
                for (int nf = 0; nf < 8; nf++)
                    mma16816(acc[mi][nf], a[s][mi], b[s][nf]);

        st = (st + 1) & 3;
    }

    #pragma unroll
    for (int mi = 0; mi < 4; mi++) {
        const int row0 = bRow + wm + mi * 16 + (lane >> 2);
        #pragma unroll
        for (int nf = 0; nf < 8; nf++) {
            const int col = bCol + wn + nf * 8 + (lane & 3) * 2;
            if constexpr (sizeof(TC) == 2) {
                *(u32*)&C[(size_t)row0 * N + col]       = packh2(acc[mi][nf][0], acc[mi][nf][1]);
                *(u32*)&C[(size_t)(row0 + 8) * N + col] = packh2(acc[mi][nf][2], acc[mi][nf][3]);
            } else {
                *(float2*)&C[(size_t)row0 * N + col]       = make_float2(acc[mi][nf][0], acc[mi][nf][1]);
                *(float2*)&C[(size_t)(row0 + 8) * N + col] = make_float2(acc[mi][nf][2], acc[mi][nf][3]);
            }
        }
    }
}

// -------- fused RMSNorm + RoPE (fp16 qkv in) -> fp16 q (pre-scaled), k, v ----
__global__ __launch_bounds__(256) void norm_rope_kernel(
    const __half* __restrict__ qkv, const int* __restrict__ positions,
    const float* __restrict__ qw, const float* __restrict__ kw,
    __half* __restrict__ qh, __half* __restrict__ kh, __half* __restrict__ vh)
{
    const int t = blockIdx.x;
    const int tid = threadIdx.x;
    const __half* row = qkv + (size_t)t * QKV_N;

    __shared__ float red[256];
    __shared__ float s_invq, s_invk;

    float sq = 0.f, sk = 0.f;
    for (int i = tid; i < H_DIM; i += 256) {
        float a = __half2float(row[i]);          sq = fmaf(a, a, sq);
        float b = __half2float(row[H_DIM + i]);  sk = fmaf(b, b, sk);
    }
    red[tid] = sq; __syncthreads();
    for (int s = 128; s > 0; s >>= 1) {
        if (tid < s) red[tid] += red[tid + s];
        __syncthreads();
    }
    if (tid == 0) s_invq = rsqrtf(red[0] / (float)H_DIM + EPS);
    __syncthreads();
    red[tid] = sk; __syncthreads();
    for (int s = 128; s > 0; s >>= 1) {
        if (tid < s) red[tid] += red[tid + s];
        __syncthreads();
    }
    if (tid == 0) s_invk = rsqrtf(red[0] / (float)H_DIM + EPS);
    __syncthreads();

    const float invq = s_invq, invk = s_invk;
    const float pos = (float)positions[t];

    for (int p = tid; p < NH * (HD / 2); p += 256) {
        const int h = p >> 6;
        const int d = p & 63;
        float invf = exp2f(-0.29580576f * (float)d);  // 500000^(-d/64)
        float ang = pos * invf;
        float c, s;
        sincosf(ang, &s, &c);

        const int i1 = h * HD + d;
        const int i2 = i1 + 64;

        float q1 = __half2float(row[i1]) * invq * qw[i1];
        float q2 = __half2float(row[i2]) * invq * qw[i2];
        float k1 = __half2float(row[H_DIM + i1]) * invk * kw[i1];
        float k2 = __half2float(row[H_DIM + i2]) * invk * kw[i2];

        const size_t ob = (size_t)t * H_DIM + h * HD + d;
        qh[ob]      = __float2half((q1 * c - q2 * s) * ATT_SCALE);
        qh[ob + 64] = __float2half((q2 * c + q1 * s) * ATT_SCALE);
        kh[ob]      = __float2half(k1 * c - k2 * s);
        kh[ob + 64] = __float2half(k2 * c + k1 * s);
    }

    for (int i = tid; i < H_DIM; i += 256)
        vh[(size_t)t * H_DIM + i] = row[2 * H_DIM + i];
}

// --------------- fp16 MMA flash attention, split-KV (R12 config) -------------
// grid (32, 16): blockIdx.x -> (qt, half), LPT-ordered (heaviest first).
// half 0: kv tiles [0, qt+1), half 1: [qt+1, 2qt+2).
#define BQ 128
#define BK 64
#define KSTR 136
#define FLASH_SMEM_BYTES ((BQ * KSTR + 4 * BK * KSTR) * 2)

__global__ __launch_bounds__(256) void flash_mma(
    const __half* __restrict__ qh, const __half* __restrict__ kh,
    const __half* __restrict__ vh, float* __restrict__ op,
    float* __restrict__ ml)
{
    const int slot = (int)blockIdx.x;            // 0..31
    const int qt   = 15 - (slot >> 1);           // heaviest (qt=15) first
    const int half = slot & 1;
    const int h = blockIdx.y;
    const int tid = threadIdx.x, wid = tid >> 5, lane = tid & 31;
    const int wm = wid * 16;

    const int kb0 = half ? (qt + 1) : 0;
    const int kb1 = half ? (2 * qt + 2) : (qt + 1);

    extern __shared__ __align__(16) __half fsm[];
    __half* Qs = fsm;
    __half* Ks = Qs + BQ * KSTR;
    __half* Vs = Ks + 2 * BK * KSTR;

    {
        const int qr = tid >> 1;
        const int qc = (tid & 1) * 8;
        const size_t qbase = (size_t)(qt * BQ + qr) * H_DIM + h * HD;
        #pragma unroll
        for (int i = 0; i < 8; i++)
            cp_async16(&Qs[qr * KSTR + (qc + i) * 8], &qh[qbase + (qc + i) * 8]);
    }
    {
        const int r  = tid >> 2;
        const int cb = (tid & 3) * 4;
        const size_t base = (size_t)(kb0 * BK + r) * H_DIM + h * HD;
        #pragma unroll
        for (int i = 0; i < 4; i++) {
            cp_async16(&Ks[r * KSTR + (cb + i) * 8], &kh[base + (cb + i) * 8]);
            cp_async16(&Vs[r * KSTR + (cb + i) * 8], &vh[base + (cb + i) * 8]);
        }
    }
    cp_commit();
    cp_wait<0>();
    __syncthreads();

    u32 qf[8][4];
    #pragma unroll
    for (int ks = 0; ks < 8; ks++)
        ldmatrix_x4(qf[ks], &Qs[(wm + (lane & 15)) * KSTR + ks * 16 + (lane >> 4) * 8]);

    float o[16][4];
    #pragma unroll
    for (int nf = 0; nf < 16; nf++)
        #pragma unroll
        for (int r = 0; r < 4; r++) o[nf][r] = 0.f;
    // init at -1e20: fully-masked tiles yield p = 0
    float m0 = -1e20f, m1 = -1e20f, l0 = 0.f, l1 = 0.f;

    for (int kb = kb0; kb < kb1; kb++) {
        if (kb > kb0) { cp_wait<0>(); __syncthreads(); }

        if (kb + 1 < kb1) {
            const int nb = (kb + 1 - kb0) & 1;
            const int r  = tid >> 2;
            const int cb4 = (tid & 3) * 4;
            const size_t base = (size_t)((kb + 1) * BK + r) * H_DIM + h * HD;
            #pragma unroll
            for (int i = 0; i < 4; i++) {
                cp_async16(&Ks[nb * BK * KSTR + r * KSTR + (cb4 + i) * 8], &kh[base + (cb4 + i) * 8]);
                cp_async16(&Vs[nb * BK * KSTR + r * KSTR + (cb4 + i) * 8], &vh[base + (cb4 + i) * 8]);
            }
            cp_commit();
        }

        const __half* Kb = Ks + ((kb - kb0) & 1) * BK * KSTR;
        const __half* Vb = Vs + ((kb - kb0) & 1) * BK * KSTR;

        float s[8][4];
        #pragma unroll
        for (int nf = 0; nf < 8; nf++)
            #pragma unroll
            for (int r = 0; r < 4; r++) s[nf][r] = 0.f;

        #pragma unroll
        for (int ks = 0; ks < 8; ks++) {
            u32 bf[8][2];
            #pragma unroll
            for (int ng = 0; ng < 4; ng++) {
                u32 r[4];
                ldmatrix_x4(r, &Kb[(ng * 16 + (lane & 7) + ((lane >> 4) << 3)) * KSTR
                                   + ks * 16 + (((lane >> 3) & 1) << 3)]);
                bf[2 * ng][0] = r[0];     bf[2 * ng][1] = r[1];
                bf[2 * ng + 1][0] = r[2]; bf[2 * ng + 1][1] = r[3];
            }
            #pragma unroll
            for (int nf = 0; nf < 8; nf++)
                mma16816(s[nf], qf[ks], bf[nf]);
        }

        // causal mask: global tiles 2qt, 2qt+1 touch the diagonal
        if (kb >= 2 * qt) {
            const int grow = qt * BQ + wm + (lane >> 2);
            #pragma unroll
            for (int nf = 0; nf < 8; nf++) {
                const int col = kb * BK + nf * 8 + (lane & 3) * 2;
                if (col     > grow)     s[nf][0] = -1e30f;
                if (col + 1 > grow)     s[nf][1] = -1e30f;
                if (col     > grow + 8) s[nf][2] = -1e30f;
                if (col + 1 > grow + 8) s[nf][3] = -1e30f;
            }
        }

        float mx0 = -1e30f, mx1 = -1e30f;
        #pragma unroll
        for (int nf = 0; nf < 8; nf++) {
            mx0 = fmaxf(mx0, fmaxf(s[nf][0], s[nf][1]));
            mx1 = fmaxf(mx1, fmaxf(s[nf][2], s[nf][3]));
        }
        mx0 = fmaxf(mx0, __shfl_xor_sync(0xffffffffu, mx0, 1));
        mx0 = fmaxf(mx0, __shfl_xor_sync(0xffffffffu, mx0, 2));
        mx1 = fmaxf(mx1, __shfl_xor_sync(0xffffffffu, mx1, 1));
        mx1 = fmaxf(mx1, __shfl_xor_sync(0xffffffffu, mx1, 2));

        const float mn0 = fmaxf(m0, mx0), mn1 = fmaxf(m1, mx1);
        const float a0 = __expf(m0 - mn0), a1 = __expf(m1 - mn1);
        m0 = mn0; m1 = mn1;

        float ps0 = 0.f, ps1 = 0.f;
        #pragma unroll
        for (int nf = 0; nf < 8; nf++) {
            s[nf][0] = __expf(s[nf][0] - m0); ps0 += s[nf][0];
            s[nf][1] = __expf(s[nf][1] - m0); ps0 += s[nf][1];
            s[nf][2] = __expf(s[nf][2] - m1); ps1 += s[nf][2];
            s[nf][3] = __expf(s[nf][3] - m1); ps1 += s[nf][3];
        }
        ps0 += __shfl_xor_sync(0xffffffffu, ps0, 1);
        ps0 += __shfl_xor_sync(0xffffffffu, ps0, 2);
        ps1 += __shfl_xor_sync(0xffffffffu, ps1, 1);
        ps1 += __shfl_xor_sync(0xffffffffu, ps1, 2);
        l0 = l0 * a0 + ps0;
        l1 = l1 * a1 + ps1;

        #pragma unroll
        for (int nf = 0; nf < 16; nf++) {
            o[nf][0] *= a0; o[nf][1] *= a0;
            o[nf][2] *= a1; o[nf][3] *= a1;
        }

        #pragma unroll
        for (int s4 = 0; s4 < 4; s4++) {
            u32 pa[4];
            pa[0] = packh2(s[2 * s4][0],     s[2 * s4][1]);
            pa[1] = packh2(s[2 * s4][2],     s[2 * s4][3]);
            pa[2] = packh2(s[2 * s4 + 1][0], s[2 * s4 + 1][1]);
            pa[3] = packh2(s[2 * s4 + 1][2], s[2 * s4 + 1][3]);
            #pragma unroll
            for (int ng = 0; ng < 8; ng++) {
                u32 r[4];
                ldmatrix_x4_trans(r, &Vb[(s4 * 16 + (lane & 15)) * KSTR
                                         + ng * 16 + (lane >> 4) * 8]);
                mma16816(o[2 * ng],     pa, &r[0]);
                mma16816(o[2 * ng + 1], pa, &r[2]);
            }
        }
    }

    // epilogue: write UNNORMALIZED partial O + (m, l) per row
    const int row0 = qt * BQ + wm + (lane >> 2);
    float* opb = op + (size_t)half * T_TOK * H_DIM;
    #pragma unroll
    for (int nf = 0; nf < 16; nf++) {
        const int col = h * HD + nf * 8 + (lane & 3) * 2;
        *(float2*)&opb[(size_t)row0 * H_DIM + col]       = make_float2(o[nf][0], o[nf][1]);
        *(float2*)&opb[(size_t)(row0 + 8) * H_DIM + col] = make_float2(o[nf][2], o[nf][3]);
    }
    if ((lane & 3) == 0) {
        float* mlb = ml + (size_t)half * T_TOK * NH * 2;
        mlb[((size_t)row0 * NH + h) * 2]           = m0;
        mlb[((size_t)row0 * NH + h) * 2 + 1]       = l0;
        mlb[((size_t)(row0 + 8) * NH + h) * 2]     = m1;
        mlb[((size_t)(row0 + 8) * NH + h) * 2 + 1] = l1;
    }
}

// ----------------------- split-KV combine (vectorized) -----------------------
__global__ __launch_bounds__(256) void flash_combine(
    const float* __restrict__ op, const float* __restrict__ ml,
    __half* __restrict__ oh)
{
    const int t = blockIdx.x;
    const int tid = threadIdx.x;
    #pragma unroll
    for (int e4 = tid; e4 < H_DIM / 4; e4 += 256) {
        const int e = e4 * 4;
        const int h = e >> 7;
        const float m0 = ml[((size_t)t * NH + h) * 2];
        const float l0 = ml[((size_t)t * NH + h) * 2 + 1];
        const float m1 = ml[(size_t)T_TOK * NH * 2 + ((size_t)t * NH + h) * 2];
        const float l1 = ml[(size_t)T_TOK * NH * 2 + ((size_t)t * NH + h) * 2 + 1];
        const float m  = fmaxf(m0, m1);
        const float e0 = __expf(m0 - m), e1 = __expf(m1 - m);
        const float inv = 1.f / (l0 * e0 + l1 * e1);
        float4 o0 = *(const float4*)&op[(size_t)t * H_DIM + e];
        float4 o1 = *(const float4*)&op[(size_t)T_TOK * H_DIM + (size_t)t * H_DIM + e];
        __half2 ha = __floats2half2_rn((o0.x * e0 + o1.x * e1) * inv,
                                       (o0.y * e0 + o1.y * e1) * inv);
        __half2 hb = __floats2half2_rn((o0.z * e0 + o1.z * e1) * inv,
                                       (o0.w * e0 + o1.w * e1) * inv);
        ((__half2*)&oh[(size_t)t * H_DIM + e])[0] = ha;
        ((__half2*)&oh[(size_t)t * H_DIM + e])[1] = hb;
    }
}

// --------------------------------- launcher ----------------------------------
extern "C" void kernel_launch(void* const* d_in, const int* in_sizes, int n_in,
                              void* d_out, int out_size)
{
    const int*   positions = (const int*)  d_in[0];
    const float* hidden    = (const float*)d_in[1];
    const float* w_qkv     = (const float*)d_in[2];
    const float* q_norm_w  = (const float*)d_in[3];
    const float* k_norm_w  = (const float*)d_in[4];
    const float* w_o       = (const float*)d_in[5];
    float* out = (float*)d_out;

    float *opart, *mlp;
    __half *qkvh, *qh, *kh, *vh, *hid_h, *wqkv_h, *wo_h, *attn_h;
    cudaGetSymbolAddress((void**)&qkvh,   g_qkvh);
    cudaGetSymbolAddress((void**)&qh,     g_qh);
    cudaGetSymbolAddress((void**)&kh,     g_kh);
    cudaGetSymbolAddress((void**)&vh,     g_vh);
    cudaGetSymbolAddress((void**)&hid_h,  g_hid_h);
    cudaGetSymbolAddress((void**)&wqkv_h, g_wqkv_h);
    cudaGetSymbolAddress((void**)&wo_h,   g_wo_h);
    cudaGetSymbolAddress((void**)&attn_h, g_attn_h);
    cudaGetSymbolAddress((void**)&opart,  g_opart);
    cudaGetSymbolAddress((void**)&mlp,    g_ml);

    // 0) fp32 -> fp16 conversions (single launch)
    {
        int total = CVT_N1 + CVT_N2 + CVT_N3;
        convert_all<<<(total + 255) / 256, 256>>>(hidden, hid_h,
                                                  w_qkv, wqkv_h, w_o, wo_h);
    }

    // 1) QKV projection (tensor cores, fp16 out)
    {
        cudaFuncSetAttribute(hgemm_w64<__half>,
                             cudaFuncAttributeMaxDynamicSharedMemorySize,
                             HG_SMEM_BYTES);
        cudaFuncSetAttribute(hgemm_w64<float>,
                             cudaFuncAttributeMaxDynamicSharedMemorySize,
                             HG_SMEM_BYTES);
        dim3 grid(QKV_N / 128, T_TOK / 128);
        hgemm_w64<__half><<<grid, 128, HG_SMEM_BYTES>>>(hid_h, wqkv_h, qkvh, T_TOK, QKV_N, H_DIM);
    }

    // 2) RMSNorm + RoPE -> fp16 q/k/v
    norm_rope_kernel<<<T_TOK, 256>>>(qkvh, positions, q_norm_w, k_norm_w, qh, kh, vh);

    // 3) causal flash attention, split-KV (tensor cores) + combine
    {
        cudaFuncSetAttribute(flash_mma,
                             cudaFuncAttributeMaxDynamicSharedMemorySize,
                             FLASH_SMEM_BYTES);
        dim3 grid(2 * (T_TOK / BQ), NH);
        flash_mma<<<grid, 256, FLASH_SMEM_BYTES>>>(qh, kh, vh, opart, mlp);
        flash_combine<<<T_TOK, 256>>>(opart, mlp, attn_h);
    }

    // 4) output projection (tensor cores, fp32 out)
    {
        dim3 grid(H_DIM / 128, T_TOK / 128);
        hgemm_w64<float><<<grid, 128, HG_SMEM_BYTES>>>(attn_h, wo_h, out, T_TOK, H_DIM, H_DIM);
    }
}

// round 17
// speedup vs baseline: 1.0871x; 1.0010x over previous
#include <cuda_runtime.h>
#include <cuda_fp16.h>
#include <stdint.h>
#include <math.h>

typedef unsigned int u32;

#define T_TOK 2048
#define H_DIM 2048
#define NH 16
#define HD 128
#define QKV_N (3 * H_DIM)   // 6144
#define EPS 1e-6f
#define ATT_SCALE 0.08838834764831843f  // 128^-0.5

// ---------------- scratch (static device globals; no allocation) -------------
__device__ __half g_qkvh[T_TOK * QKV_N];    // [T, 3H] fp16 (GEMM writes fp16)
__device__ __half g_qh[T_TOK * H_DIM];      // post norm+rope, pre-scaled
__device__ __half g_kh[T_TOK * H_DIM];
__device__ __half g_vh[T_TOK * H_DIM];
__device__ __half g_hid_h[T_TOK * H_DIM];
__device__ __half g_wqkv_h[H_DIM * QKV_N];
__device__ __half g_wo_h[H_DIM * H_DIM];
__device__ __half g_attn_h[T_TOK * H_DIM];
__device__ float  g_opart[2 * T_TOK * H_DIM];        // split-KV partial O
__device__ float  g_ml[2 * T_TOK * NH * 2];          // per-row (m, l) per half

// ---------------- merged f32 -> f16 conversion (3 tensors, 1 launch) ---------
#define CVT_N1 (T_TOK * H_DIM / 4)     // hidden
#define CVT_N2 (H_DIM * QKV_N / 4)     // w_qkv
#define CVT_N3 (H_DIM * H_DIM / 4)     // w_o
__global__ __launch_bounds__(256) void convert_all(
    const float* __restrict__ in1, __half* __restrict__ out1,
    const float* __restrict__ in2, __half* __restrict__ out2,
    const float* __restrict__ in3, __half* __restrict__ out3)
{
    int i = blockIdx.x * 256 + threadIdx.x;
    const float* in; __half* out; int idx;
    if (i < CVT_N1)                 { in = in1; out = out1; idx = i; }
    else if (i < CVT_N1 + CVT_N2)   { in = in2; out = out2; idx = i - CVT_N1; }
    else if (i < CVT_N1 + CVT_N2 + CVT_N3) { in = in3; out = out3; idx = i - CVT_N1 - CVT_N2; }
    else return;
    float4 v = ((const float4*)in)[idx];
    ((__half2*)out)[2 * idx]     = __floats2half2_rn(v.x, v.y);
    ((__half2*)out)[2 * idx + 1] = __floats2half2_rn(v.z, v.w);
}

// ------------------------- PTX wrappers --------------------------------------
__device__ __forceinline__ void cp_async16(void* sptr, const void* gptr) {
    u32 s = (u32)__cvta_generic_to_shared(sptr);
    asm volatile("cp.async.cg.shared.global [%0], [%1], 16;\n" :: "r"(s), "l"(gptr));
}
__device__ __forceinline__ void cp_commit() {
    asm volatile("cp.async.commit_group;\n");
}
template <int N>
__device__ __forceinline__ void cp_wait() {
    asm volatile("cp.async.wait_group %0;\n" :: "n"(N));
}
__device__ __forceinline__ void ldmatrix_x4(u32* r, const void* sptr) {
    u32 s = (u32)__cvta_generic_to_shared(sptr);
    asm volatile("ldmatrix.sync.aligned.m8n8.x4.shared.b16 {%0,%1,%2,%3}, [%4];\n"
                 : "=r"(r[0]), "=r"(r[1]), "=r"(r[2]), "=r"(r[3]) : "r"(s));
}
__device__ __forceinline__ void ldmatrix_x4_trans(u32* r, const void* sptr) {
    u32 s = (u32)__cvta_generic_to_shared(sptr);
    asm volatile("ldmatrix.sync.aligned.m8n8.x4.trans.shared.b16 {%0,%1,%2,%3}, [%4];\n"
                 : "=r"(r[0]), "=r"(r[1]), "=r"(r[2]), "=r"(r[3]) : "r"(s));
}
__device__ __forceinline__ void mma16816(float* d, const u32* a, const u32* b) {
    asm volatile(
        "mma.sync.aligned.m16n8k16.row.col.f32.f16.f16.f32 "
        "{%0,%1,%2,%3}, {%4,%5,%6,%7}, {%8,%9}, {%0,%1,%2,%3};\n"
        : "+f"(d[0]), "+f"(d[1]), "+f"(d[2]), "+f"(d[3])
        : "r"(a[0]), "r"(a[1]), "r"(a[2]), "r"(a[3]), "r"(b[0]), "r"(b[1]));
}
__device__ __forceinline__ u32 packh2(float a, float b) {
    __half2 h = __floats2half2_rn(a, b);
    return *reinterpret_cast<u32*>(&h);
}

// ---- fp16 GEMM: CTA 128x128, 4 warps (64x64), BK=32, 4-stage, 1 barrier -----
// Templated epilogue: TC = float (fp32 out) or __half (fp16 out).
#define ASTRIDE 40
#define BSTRIDE 136
#define HG_STAGE_A (128 * ASTRIDE)           // halves
#define HG_STAGE_B (32 * BSTRIDE)
#define HG_STAGE   (HG_STAGE_A + HG_STAGE_B) // 9472 halves
#define HG_STAGES  4
#define HG_SMEM_BYTES (HG_STAGES * HG_STAGE * 2)   // 75776 B

template <typename TC>
__global__ __launch_bounds__(128, 2) void hgemm_w64(
    const __half* __restrict__ A, const __half* __restrict__ B,
    TC* __restrict__ C, int M, int N, int K)
{
    extern __shared__ __align__(16) __half hsm[];

    const int tid  = threadIdx.x;
    const int wid  = tid >> 5;
    const int lane = tid & 31;
    const int wm = (wid & 1) * 64;
    const int wn = (wid >> 1) * 64;
    const int bRow = blockIdx.y * 128;
    const int bCol = blockIdx.x * 128;

    const int a_r0 = tid >> 2;
    const int a_c  = (tid & 3) * 8;
    const int b_r0 = tid >> 4;
    const int b_c  = (tid & 15) * 8;

    float acc[4][8][4];
    #pragma unroll
    for (int mi = 0; mi < 4; mi++)
        #pragma unroll
        for (int nf = 0; nf < 8; nf++)
            #pragma unroll
            for (int r = 0; r < 4; r++) acc[mi][nf][r] = 0.f;

    const int NT = K / 32;

    auto load_tile = [&](int kt, int st) {
        __half* As = hsm + st * HG_STAGE;
        __half* Bs = As + HG_STAGE_A;
        const int kb = kt * 32;
        #pragma unroll
        for (int p = 0; p < 4; p++) {
            int ar = a_r0 + p * 32;
            cp_async16(&As[ar * ASTRIDE + a_c], A + (size_t)(bRow + ar) * K + kb + a_c);
            int br = b_r0 + p * 8;
            cp_async16(&Bs[br * BSTRIDE + b_c], B + (size_t)(kb + br) * N + bCol + b_c);
        }
    };

    load_tile(0, 0); cp_commit();
    load_tile(1, 1); cp_commit();
    load_tile(2, 2); cp_commit();

    int st = 0;
    for (int kt = 0; kt < NT; kt++) {
        cp_wait<2>();
        __syncthreads();

        if (kt + 3 < NT) load_tile(kt + 3, (st + 3) & 3);
        cp_commit();

        const __half* As = hsm + st * HG_STAGE;
        const __half* Bs = As + HG_STAGE_A;

        u32 a[2][4][4];
        u32 b[2][8][2];
        #pragma unroll
        for (int s = 0; s < 2; s++) {
            const int ko = s * 16;
            #pragma unroll
            for (int mi = 0; mi < 4; mi++)
                ldmatrix_x4(a[s][mi],
                    &As[(wm + mi * 16 + (lane & 15)) * ASTRIDE + ko + (lane >> 4) * 8]);
            #pragma unroll
            for (int ng = 0; ng < 4; ng++) {
                u32 r[4];
                ldmatrix_x4_trans(r,
                    &Bs[(ko + (lane & 15)) * BSTRIDE + wn + ng * 16 + (lane >> 4) * 8]);
                b[s][2 * ng][0]     = r[0]; b[s][2 * ng][1]     = r[1];
                b[s][2 * ng + 1][0] = r[2]; b[s][2 * ng + 1][1] = r[3];
            }
        }
        #pragma unroll
        for (int s = 0; s < 2; s++)
            #pragma unroll
            for (int mi = 0; mi < 4; mi++)
                #pragma unroll
                for (int nf = 0; nf < 8; nf++)
                    mma16816(acc[mi][nf], a[s][mi], b[s][nf]);

        st = (st + 1) & 3;
    }

    #pragma unroll
    for (int mi = 0; mi < 4; mi++) {
        const int row0 = bRow + wm + mi * 16 + (lane >> 2);
        #pragma unroll
        for (int nf = 0; nf < 8; nf++) {
            const int col = bCol + wn + nf * 8 + (lane & 3) * 2;
            if constexpr (sizeof(TC) == 2) {
                *(u32*)&C[(size_t)row0 * N + col]       = packh2(acc[mi][nf][0], acc[mi][nf][1]);
                *(u32*)&C[(size_t)(row0 + 8) * N + col] = packh2(acc[mi][nf][2], acc[mi][nf][3]);
            } else {
                *(float2*)&C[(size_t)row0 * N + col]       = make_float2(acc[mi][nf][0], acc[mi][nf][1]);
                *(float2*)&C[(size_t)(row0 + 8) * N + col] = make_float2(acc[mi][nf][2], acc[mi][nf][3]);
            }
        }
    }
}

// -------- fused RMSNorm + RoPE (fp16 qkv in) -> fp16 q (pre-scaled), k, v ----
__global__ __launch_bounds__(256) void norm_rope_kernel(
    const __half* __restrict__ qkv, const int* __restrict__ positions,
    const float* __restrict__ qw, const float* __restrict__ kw,
    __half* __restrict__ qh, __half* __restrict__ kh, __half* __restrict__ vh)
{
    const int t = blockIdx.x;
    const int tid = threadIdx.x;
    const __half* row = qkv + (size_t)t * QKV_N;

    __shared__ float red[256];
    __shared__ float s_invq, s_invk;

    float sq = 0.f, sk = 0.f;
    for (int i = tid; i < H_DIM; i += 256) {
        float a = __half2float(row[i]);          sq = fmaf(a, a, sq);
        float b = __half2float(row[H_DIM + i]);  sk = fmaf(b, b, sk);
    }
    red[tid] = sq; __syncthreads();
    for (int s = 128; s > 0; s >>= 1) {
        if (tid < s) red[tid] += red[tid + s];
        __syncthreads();
    }
    if (tid == 0) s_invq = rsqrtf(red[0] / (float)H_DIM + EPS);
    __syncthreads();
    red[tid] = sk; __syncthreads();
    for (int s = 128; s > 0; s >>= 1) {
        if (tid < s) red[tid] += red[tid + s];
        __syncthreads();
    }
    if (tid == 0) s_invk = rsqrtf(red[0] / (float)H_DIM + EPS);
    __syncthreads();

    const float invq = s_invq, invk = s_invk;
    const float pos = (float)positions[t];

    for (int p = tid; p < NH * (HD / 2); p += 256) {
        const int h = p >> 6;
        const int d = p & 63;
        float invf = exp2f(-0.29580576f * (float)d);  // 500000^(-d/64)
        float ang = pos * invf;
        float c, s;
        sincosf(ang, &s, &c);

        const int i1 = h * HD + d;
        const int i2 = i1 + 64;

        float q1 = __half2float(row[i1]) * invq * qw[i1];
        float q2 = __half2float(row[i2]) * invq * qw[i2];
        float k1 = __half2float(row[H_DIM + i1]) * invk * kw[i1];
        float k2 = __half2float(row[H_DIM + i2]) * invk * kw[i2];

        const size_t ob = (size_t)t * H_DIM + h * HD + d;
        qh[ob]      = __float2half((q1 * c - q2 * s) * ATT_SCALE);
        qh[ob + 64] = __float2half((q2 * c + q1 * s) * ATT_SCALE);
        kh[ob]      = __float2half(k1 * c - k2 * s);
        kh[ob + 64] = __float2half(k2 * c + k1 * s);
    }

    for (int i = tid; i < H_DIM; i += 256)
        vh[(size_t)t * H_DIM + i] = row[2 * H_DIM + i];
}

// --------------- fp16 MMA flash attention, split-KV, V-frag pipeline ---------
// grid (32, 16): blockIdx.x -> (qt, half), LPT-ordered (heaviest first).
// half 0: kv tiles [0, qt+1), half 1: [qt+1, 2qt+2).
#define BQ 128
#define BK 64
#define KSTR 136
#define FLASH_SMEM_BYTES ((BQ * KSTR + 4 * BK * KSTR) * 2)

__global__ __launch_bounds__(256) void flash_mma(
    const __half* __restrict__ qh, const __half* __restrict__ kh,
    const __half* __restrict__ vh, float* __restrict__ op,
    float* __restrict__ ml)
{
    const int slot = (int)blockIdx.x;            // 0..31
    const int qt   = 15 - (slot >> 1);           // heaviest (qt=15) first
    const int half = slot & 1;
    const int h = blockIdx.y;
    const int tid = threadIdx.x, wid = tid >> 5, lane = tid & 31;
    const int wm = wid * 16;

    const int kb0 = half ? (qt + 1) : 0;
    const int kb1 = half ? (2 * qt + 2) : (qt + 1);

    extern __shared__ __align__(16) __half fsm[];
    __half* Qs = fsm;
    __half* Ks = Qs + BQ * KSTR;
    __half* Vs = Ks + 2 * BK * KSTR;

    {
        const int qr = tid >> 1;
        const int qc = (tid & 1) * 8;
        const size_t qbase = (size_t)(qt * BQ + qr) * H_DIM + h * HD;
        #pragma unroll
        for (int i = 0; i < 8; i++)
            cp_async16(&Qs[qr * KSTR + (qc + i) * 8], &qh[qbase + (qc + i) * 8]);
    }
    {
        const int r  = tid >> 2;
        const int cb = (tid & 3) * 4;
        const size_t base = (size_t)(kb0 * BK + r) * H_DIM + h * HD;
        #pragma unroll
        for (int i = 0; i < 4; i++) {
            cp_async16(&Ks[r * KSTR + (cb + i) * 8], &kh[base + (cb + i) * 8]);
            cp_async16(&Vs[r * KSTR + (cb + i) * 8], &vh[base + (cb + i) * 8]);
        }
    }
    cp_commit();
    cp_wait<0>();
    __syncthreads();

    u32 qf[8][4];
    #pragma unroll
    for (int ks = 0; ks < 8; ks++)
        ldmatrix_x4(qf[ks], &Qs[(wm + (lane & 15)) * KSTR + ks * 16 + (lane >> 4) * 8]);

    float o[16][4];
    #pragma unroll
    for (int nf = 0; nf < 16; nf++)
        #pragma unroll
        for (int r = 0; r < 4; r++) o[nf][r] = 0.f;
    // init at -1e20: fully-masked tiles yield p = 0
    float m0 = -1e20f, m1 = -1e20f, l0 = 0.f, l1 = 0.f;

    for (int kb = kb0; kb < kb1; kb++) {
        if (kb > kb0) { cp_wait<0>(); __syncthreads(); }

        if (kb + 1 < kb1) {
            const int nb = (kb + 1 - kb0) & 1;
            const int r  = tid >> 2;
            const int cb4 = (tid & 3) * 4;
            const size_t base = (size_t)((kb + 1) * BK + r) * H_DIM + h * HD;
            #pragma unroll
            for (int i = 0; i < 4; i++) {
                cp_async16(&Ks[nb * BK * KSTR + r * KSTR + (cb4 + i) * 8], &kh[base + (cb4 + i) * 8]);
                cp_async16(&Vs[nb * BK * KSTR + r * KSTR + (cb4 + i) * 8], &vh[base + (cb4 + i) * 8]);
            }
            cp_commit();
        }

        const __half* Kb = Ks + ((kb - kb0) & 1) * BK * KSTR;
        const __half* Vb = Vs + ((kb - kb0) & 1) * BK * KSTR;

        float s[8][4];
        #pragma unroll
        for (int nf = 0; nf < 8; nf++)
            #pragma unroll
            for (int r = 0; r < 4; r++) s[nf][r] = 0.f;

        #pragma unroll
        for (int ks = 0; ks < 8; ks++) {
            u32 bf[8][2];
            #pragma unroll
            for (int ng = 0; ng < 4; ng++) {
                u32 r[4];
                ldmatrix_x4(r, &Kb[(ng * 16 + (lane & 7) + ((lane >> 4) << 3)) * KSTR
                                   + ks * 16 + (((lane >> 3) & 1) << 3)]);
                bf[2 * ng][0] = r[0];     bf[2 * ng][1] = r[1];
                bf[2 * ng + 1][0] = r[2]; bf[2 * ng + 1][1] = r[3];
            }
            #pragma unroll
            for (int nf = 0; nf < 8; nf++)
                mma16816(s[nf], qf[ks], bf[nf]);
        }

        // ---- preload V fragments for s4-group 0 (overlaps softmax below) ----
        u32 vf[2][8][4];
        #pragma unroll
        for (int ng = 0; ng < 8; ng++)
            ldmatrix_x4_trans(vf[0][ng], &Vb[(lane & 15) * KSTR
                                             + ng * 16 + (lane >> 4) * 8]);

        // causal mask: global tiles 2qt, 2qt+1 touch the diagonal
        if (kb >= 2 * qt) {
            const int grow = qt * BQ + wm + (lane >> 2);
            #pragma unroll
            for (int nf = 0; nf < 8; nf++) {
                const int col = kb * BK + nf * 8 + (lane & 3) * 2;
                if (col     > grow)     s[nf][0] = -1e30f;
                if (col + 1 > grow)     s[nf][1] = -1e30f;
                if (col     > grow + 8) s[nf][2] = -1e30f;
                if (col + 1 > grow + 8) s[nf][3] = -1e30f;
            }
        }

        float mx0 = -1e30f, mx1 = -1e30f;
        #pragma unroll
        for (int nf = 0; nf < 8; nf++) {
            mx0 = fmaxf(mx0, fmaxf(s[nf][0], s[nf][1]));
            mx1 = fmaxf(mx1, fmaxf(s[nf][2], s[nf][3]));
        }
        mx0 = fmaxf(mx0, __shfl_xor_sync(0xffffffffu, mx0, 1));
        mx0 = fmaxf(mx0, __shfl_xor_sync(0xffffffffu, mx0, 2));
        mx1 = fmaxf(mx1, __shfl_xor_sync(0xffffffffu, mx1, 1));
        mx1 = fmaxf(mx1, __shfl_xor_sync(0xffffffffu, mx1, 2));

        const float mn0 = fmaxf(m0, mx0), mn1 = fmaxf(m1, mx1);
        const float a0 = __expf(m0 - mn0), a1 = __expf(m1 - mn1);
        m0 = mn0; m1 = mn1;

        float ps0 = 0.f, ps1 = 0.f;
        #pragma unroll
        for (int nf = 0; nf < 8; nf++) {
            s[nf][0] = __expf(s[nf][0] - m0); ps0 += s[nf][0];
            s[nf][1] = __expf(s[nf][1] - m0); ps0 += s[nf][1];
            s[nf][2] = __expf(s[nf][2] - m1); ps1 += s[nf][2];
            s[nf][3] = __expf(s[nf][3] - m1); ps1 += s[nf][3];
        }
        ps0 += __shfl_xor_sync(0xffffffffu, ps0, 1);
        ps0 += __shfl_xor_sync(0xffffffffu, ps0, 2);
        ps1 += __shfl_xor_sync(0xffffffffu, ps1, 1);
        ps1 += __shfl_xor_sync(0xffffffffu, ps1, 2);
        l0 = l0 * a0 + ps0;
        l1 = l1 * a1 + ps1;

        #pragma unroll
        for (int nf = 0; nf < 16; nf++) {
            o[nf][0] *= a0; o[nf][1] *= a0;
            o[nf][2] *= a1; o[nf][3] *= a1;
        }

        // ---- PV with pipelined V fragments ----
        #pragma unroll
        for (int s4 = 0; s4 < 4; s4++) {
            if (s4 < 3) {
                #pragma unroll
                for (int ng = 0; ng < 8; ng++)
                    ldmatrix_x4_trans(vf[(s4 + 1) & 1][ng],
                        &Vb[((s4 + 1) * 16 + (lane & 15)) * KSTR
                            + ng * 16 + (lane >> 4) * 8]);
            }
            u32 pa[4];
            pa[0] = packh2(s[2 * s4][0],     s[2 * s4][1]);
            pa[1] = packh2(s[2 * s4][2],     s[2 * s4][3]);
            pa[2] = packh2(s[2 * s4 + 1][0], s[2 * s4 + 1][1]);
            pa[3] = packh2(s[2 * s4 + 1][2], s[2 * s4 + 1][3]);
            #pragma unroll
            for (int ng = 0; ng < 8; ng++) {
                mma16816(o[2 * ng],     pa, &vf[s4 & 1][ng][0]);
                mma16816(o[2 * ng + 1], pa, &vf[s4 & 1][ng][2]);
            }
        }
    }

    // epilogue: write UNNORMALIZED partial O + (m, l) per row
    const int row0 = qt * BQ + wm + (lane >> 2);
    float* opb = op + (size_t)half * T_TOK * H_DIM;
    #pragma unroll
    for (int nf = 0; nf < 16; nf++) {
        const int col = h * HD + nf * 8 + (lane & 3) * 2;
        *(float2*)&opb[(size_t)row0 * H_DIM + col]       = make_float2(o[nf][0], o[nf][1]);
        *(float2*)&opb[(size_t)(row0 + 8) * H_DIM + col] = make_float2(o[nf][2], o[nf][3]);
    }
    if ((lane & 3) == 0) {
        float* mlb = ml + (size_t)half * T_TOK * NH * 2;
        mlb[((size_t)row0 * NH + h) * 2]           = m0;
        mlb[((size_t)row0 * NH + h) * 2 + 1]       = l0;
        mlb[((size_t)(row0 + 8) * NH + h) * 2]     = m1;
        mlb[((size_t)(row0 + 8) * NH + h) * 2 + 1] = l1;
    }
}

// ----------------------- split-KV combine (vectorized) -----------------------
__global__ __launch_bounds__(256) void flash_combine(
    const float* __restrict__ op, const float* __restrict__ ml,
    __half* __restrict__ oh)
{
    const int t = blockIdx.x;
    const int tid = threadIdx.x;
    #pragma unroll
    for (int e4 = tid; e4 < H_DIM / 4; e4 += 256) {
        const int e = e4 * 4;
        const int h = e >> 7;
        const float m0 = ml[((size_t)t * NH + h) * 2];
        const float l0 = ml[((size_t)t * NH + h) * 2 + 1];
        const float m1 = ml[(size_t)T_TOK * NH * 2 + ((size_t)t * NH + h) * 2];
        const float l1 = ml[(size_t)T_TOK * NH * 2 + ((size_t)t * NH + h) * 2 + 1];
        const float m  = fmaxf(m0, m1);
        const float e0 = __expf(m0 - m), e1 = __expf(m1 - m);
        const float inv = 1.f / (l0 * e0 + l1 * e1);
        float4 o0 = *(const float4*)&op[(size_t)t * H_DIM + e];
        float4 o1 = *(const float4*)&op[(size_t)T_TOK * H_DIM + (size_t)t * H_DIM + e];
        __half2 ha = __floats2half2_rn((o0.x * e0 + o1.x * e1) * inv,
                                       (o0.y * e0 + o1.y * e1) * inv);
        __half2 hb = __floats2half2_rn((o0.z * e0 + o1.z * e1) * inv,
                                       (o0.w * e0 + o1.w * e1) * inv);
        ((__half2*)&oh[(size_t)t * H_DIM + e])[0] = ha;
        ((__half2*)&oh[(size_t)t * H_DIM + e])[1] = hb;
    }
}

// --------------------------------- launcher ----------------------------------
extern "C" void kernel_launch(void* const* d_in, const int* in_sizes, int n_in,
                              void* d_out, int out_size)
{
    const int*   positions = (const int*)  d_in[0];
    const float* hidden    = (const float*)d_in[1];
    const float* w_qkv     = (const float*)d_in[2];
    const float* q_norm_w  = (const float*)d_in[3];
    const float* k_norm_w  = (const float*)d_in[4];
    const float* w_o       = (const float*)d_in[5];
    float* out = (float*)d_out;

    float *opart, *mlp;
    __half *qkvh, *qh, *kh, *vh, *hid_h, *wqkv_h, *wo_h, *attn_h;
    cudaGetSymbolAddress((void**)&qkvh,   g_qkvh);
    cudaGetSymbolAddress((void**)&qh,     g_qh);
    cudaGetSymbolAddress((void**)&kh,     g_kh);
    cudaGetSymbolAddress((void**)&vh,     g_vh);
    cudaGetSymbolAddress((void**)&hid_h,  g_hid_h);
    cudaGetSymbolAddress((void**)&wqkv_h, g_wqkv_h);
    cudaGetSymbolAddress((void**)&wo_h,   g_wo_h);
    cudaGetSymbolAddress((void**)&attn_h, g_attn_h);
    cudaGetSymbolAddress((void**)&opart,  g_opart);
    cudaGetSymbolAddress((void**)&mlp,    g_ml);

    // 0) fp32 -> fp16 conversions (single launch)
    {
        int total = CVT_N1 + CVT_N2 + CVT_N3;
        convert_all<<<(total + 255) / 256, 256>>>(hidden, hid_h,
                                                  w_qkv, wqkv_h, w_o, wo_h);
    }

    // 1) QKV projection (tensor cores, fp16 out)
    {
        cudaFuncSetAttribute(hgemm_w64<__half>,
                             cudaFuncAttributeMaxDynamicSharedMemorySize,
                             HG_SMEM_BYTES);
        cudaFuncSetAttribute(hgemm_w64<float>,
                             cudaFuncAttributeMaxDynamicSharedMemorySize,
                             HG_SMEM_BYTES);
        dim3 grid(QKV_N / 128, T_TOK / 128);
        hgemm_w64<__half><<<grid, 128, HG_SMEM_BYTES>>>(hid_h, wqkv_h, qkvh, T_TOK, QKV_N, H_DIM);
    }

    // 2) RMSNorm + RoPE -> fp16 q/k/v
    norm_rope_kernel<<<T_TOK, 256>>>(qkvh, positions, q_norm_w, k_norm_w, qh, kh, vh);

    // 3) causal flash attention, split-KV (tensor cores) + combine
    {
        cudaFuncSetAttribute(flash_mma,
                             cudaFuncAttributeMaxDynamicSharedMemorySize,
                             FLASH_SMEM_BYTES);
        dim3 grid(2 * (T_TOK / BQ), NH);
        flash_mma<<<grid, 256, FLASH_SMEM_BYTES>>>(qh, kh, vh, opart, mlp);
        flash_combine<<<T_TOK, 256>>>(opart, mlp, attn_h);
    }

    // 4) output projection (tensor cores, fp32 out)
    {
        dim3 grid(H_DIM / 128, T_TOK / 128);
        hgemm_w64<float><<<grid, 128, HG_SMEM_BYTES>>>(attn_h, wo_h, out, T_TOK, H_DIM, H_DIM);
    }
}